// round 11
// baseline (speedup 1.0000x reference)
#include <cuda_runtime.h>
#include <cstdint>
#include <cstdlib>

#define BATCH   8
#define NSEQ    1024
#define EMB     768
#define NHEADS  12
#define HDIM    64
#define MTOT    (BATCH * NSEQ)
#define HSTRIDE (NSEQ * HDIM)     // 65536
#define SLOT    (3 * NHEADS * NSEQ * HDIM)   // one batch of Q,K,V

// Scratch: TWO ping-pong slots of one batch each. 18.9 MiB total (proven).
// Layout per slot: [sel(3)][head(12)][n(1024)][d(64)]
__device__ float g_s[2 * SLOT];

namespace {
struct EagerLoad { EagerLoad() { setenv("CUDA_MODULE_LOADING", "EAGER", 1); } };
EagerLoad eager_load_instance_;
}

// ---------------------------------------------------------------------------
// tf32 helpers
// ---------------------------------------------------------------------------
__device__ __forceinline__ unsigned f2tf(float x) {
    unsigned r;
    asm("cvt.rna.tf32.f32 %0, %1;" : "=r"(r) : "f"(x));
    return r;
}
__device__ __forceinline__ float f2tff(float x) { return __uint_as_float(f2tf(x)); }

__device__ __forceinline__ void mma8(float* c, const unsigned* a, const unsigned* b) {
    asm volatile(
        "mma.sync.aligned.m16n8k8.row.col.f32.tf32.tf32.f32 "
        "{%0,%1,%2,%3}, {%4,%5,%6,%7}, {%8,%9}, {%0,%1,%2,%3};\n"
        : "+f"(c[0]), "+f"(c[1]), "+f"(c[2]), "+f"(c[3])
        : "r"(a[0]), "r"(a[1]), "r"(a[2]), "r"(a[3]), "r"(b[0]), "r"(b[1]));
}

__device__ __forceinline__ float4 hi4(float4 v) {
    return make_float4(f2tff(v.x), f2tff(v.y), f2tff(v.z), f2tff(v.w));
}
__device__ __forceinline__ float4 lo4(float4 v, float4 h) {
    return make_float4(f2tff(v.x - h.x), f2tff(v.y - h.y),
                       f2tff(v.z - h.z), f2tff(v.w - h.w));
}

// ---------------------------------------------------------------------------
// Fused QKV GEMM (tf32x2: x hi+lo at fragment load, W hi only) for ONE batch.
// Grid (18, 8). Writes into ping-pong slot `buf`.
// ---------------------------------------------------------------------------
#define GEMM_SMEM (4 * 128 * 36 * 4)   // Araw[2] + Bh[2] = 73728 B

__global__ __launch_bounds__(256) void qkv_gemm_kernel(
    const float* __restrict__ x,
    const float* __restrict__ wq, const float* __restrict__ bq,
    const float* __restrict__ wk, const float* __restrict__ bk,
    const float* __restrict__ wv, const float* __restrict__ bv,
    int batch, int buf)
{
    extern __shared__ float sm[];
    float* Ar = sm;                    // [2][128*36] raw fp32
    float* Bh = sm + 2 * 128 * 36;     // [2][128*36] tf32-hi

    const int bx = blockIdx.x;         // 0..17
    const int by = blockIdx.y;         // 0..7
    const int sel = bx / 6;
    const int bxx = bx % 6;
    const float* W    = (sel == 0) ? wq : (sel == 1) ? wk : wv;
    const float* bias = (sel == 0) ? bq : (sel == 1) ? bk : bv;
    const float* A = x + (size_t)batch * NSEQ * EMB;

    const int tid = threadIdx.x;
    const int lane = tid & 31;
    const int w = tid >> 5;
    const int wm = w & 3;
    const int wn = w >> 2;
    const int gid = lane >> 2;
    const int tig = lane & 3;

    const int lrow = tid >> 1;
    const int lcol = (tid & 1) * 16;

    const float* Ag = A + (size_t)(by * 128 + lrow) * EMB + lcol;
    const float* Wg = W + (size_t)(bxx * 128 + lrow) * EMB + lcol;

    float acc[2][8][4];
#pragma unroll
    for (int mt = 0; mt < 2; mt++)
#pragma unroll
        for (int nt = 0; nt < 8; nt++)
#pragma unroll
            for (int i = 0; i < 4; i++) acc[mt][nt][i] = 0.f;

    float4 ra[4], rb[4];
#pragma unroll
    for (int j = 0; j < 4; j++) {
        ra[j] = *(const float4*)(Ag + j * 4);
        rb[j] = *(const float4*)(Wg + j * 4);
    }
#pragma unroll
    for (int j = 0; j < 4; j++) {
        *(float4*)(Ar + lrow * 36 + lcol + j * 4) = ra[j];
        *(float4*)(Bh + lrow * 36 + lcol + j * 4) = hi4(rb[j]);
    }
    __syncthreads();

    const int NKT = EMB / 32;   // 24
    for (int kt = 0; kt < NKT; kt++) {
        const int cur = kt & 1;
        if (kt + 1 < NKT) {
#pragma unroll
            for (int j = 0; j < 4; j++) {
                ra[j] = *(const float4*)(Ag + (kt + 1) * 32 + j * 4);
                rb[j] = *(const float4*)(Wg + (kt + 1) * 32 + j * 4);
            }
        }
        const float* Ab = Ar + cur * 128 * 36;
        const float* Bb = Bh + cur * 128 * 36;
#pragma unroll
        for (int ks = 0; ks < 4; ks++) {
            unsigned afh[2][4], afl[2][4], bfh[8][2];
#pragma unroll
            for (int mt = 0; mt < 2; mt++) {
                const int base = (wm * 32 + mt * 16) * 36 + ks * 8;
                float a0 = Ab[base + gid * 36 + tig];
                float a1 = Ab[base + (gid + 8) * 36 + tig];
                float a2 = Ab[base + gid * 36 + tig + 4];
                float a3 = Ab[base + (gid + 8) * 36 + tig + 4];
                float h0 = f2tff(a0), h1 = f2tff(a1), h2 = f2tff(a2), h3 = f2tff(a3);
                afh[mt][0] = __float_as_uint(h0); afl[mt][0] = f2tf(a0 - h0);
                afh[mt][1] = __float_as_uint(h1); afl[mt][1] = f2tf(a1 - h1);
                afh[mt][2] = __float_as_uint(h2); afl[mt][2] = f2tf(a2 - h2);
                afh[mt][3] = __float_as_uint(h3); afl[mt][3] = f2tf(a3 - h3);
            }
#pragma unroll
            for (int nt = 0; nt < 8; nt++) {
                const int base = (wn * 64 + nt * 8 + gid) * 36 + ks * 8;
                bfh[nt][0] = __float_as_uint(Bb[base + tig]);
                bfh[nt][1] = __float_as_uint(Bb[base + tig + 4]);
            }
#pragma unroll
            for (int mt = 0; mt < 2; mt++)
#pragma unroll
                for (int nt = 0; nt < 8; nt++) {
                    mma8(acc[mt][nt], afh[mt], bfh[nt]);
                    mma8(acc[mt][nt], afl[mt], bfh[nt]);
                }
        }
        if (kt + 1 < NKT) {
            const int nxt = cur ^ 1;
#pragma unroll
            for (int j = 0; j < 4; j++) {
                *(float4*)(Ar + nxt * 128 * 36 + lrow * 36 + lcol + j * 4) = ra[j];
                *(float4*)(Bh + nxt * 128 * 36 + lrow * 36 + lcol + j * 4) = hi4(rb[j]);
            }
            __syncthreads();
        }
    }

#pragma unroll
    for (int mt = 0; mt < 2; mt++) {
        const int n = by * 128 + wm * 32 + mt * 16 + gid;   // 0..1023
#pragma unroll
        for (int nt = 0; nt < 8; nt++) {
            const int wcol = bxx * 128 + wn * 64 + nt * 8 + 2 * tig;
            const float b0 = bias[wcol], b1 = bias[wcol + 1];
            const int h_ = wcol >> 6, d_ = wcol & 63;
            float* dst = g_s + (size_t)buf * SLOT +
                (((size_t)sel * NHEADS + h_) * NSEQ + n) * HDIM + d_;
            *(float2*)dst = make_float2(acc[mt][nt][0] + b0, acc[mt][nt][1] + b1);
            *(float2*)(dst + 8 * HDIM) =
                make_float2(acc[mt][nt][2] + b0, acc[mt][nt][3] + b1);
        }
    }
}

// ---------------------------------------------------------------------------
// Flash attention for ONE batch from slot `buf`: S = QK^T tf32x3 (K hi/lo
// precomputed at tile load), P*V single tf32. Grid (16, 12); 128 threads.
// ---------------------------------------------------------------------------
#define KPITCH 68
#define VPITCH 72
#define PPITCH 68
#define FLASH_SMEM ((2 * 64 * KPITCH + 64 * VPITCH + 4 * 16 * PPITCH) * 4)  // 70656

__global__ __launch_bounds__(128, 3) void flash_kernel(
    float* __restrict__ out, int batch, int buf)
{
    extern __shared__ float sm[];
    float* ksh = sm;                         // [64][68] K hi
    float* ksl = ksh + 64 * KPITCH;          // [64][68] K lo
    float* vsh = ksl + 64 * KPITCH;          // [64][72] V hi
    float* psh = vsh + 64 * VPITCH;          // [4][16][68] P

    const int h = blockIdx.y;
    const int q0 = blockIdx.x * 64;
    const int tid = threadIdx.x;
    const int lane = tid & 31;
    const int w = tid >> 5;                  // 0..3
    const int gid = lane >> 2;
    const int tig = lane & 3;
    float* pw = psh + w * 16 * PPITCH;

    const float* base_s = g_s + (size_t)buf * SLOT;
    const float* qg = base_s + (size_t)h * HSTRIDE;
    const float* kg = base_s + (size_t)(NHEADS + h) * HSTRIDE;
    const float* vg = base_s + (size_t)(2 * NHEADS + h) * HSTRIDE;

    const int r0 = q0 + w * 16 + gid;

    // Q fragments hi/lo in registers (reused across all 16 key tiles)
    unsigned qah[8][4], qal[8][4];
#pragma unroll
    for (int kk = 0; kk < 8; kk++) {
        const int c = kk * 8 + tig;
        float v0 = qg[(size_t)r0 * HDIM + c];
        float v1 = qg[(size_t)(r0 + 8) * HDIM + c];
        float v2 = qg[(size_t)r0 * HDIM + c + 4];
        float v3 = qg[(size_t)(r0 + 8) * HDIM + c + 4];
        float h0 = f2tff(v0), h1 = f2tff(v1), h2 = f2tff(v2), h3 = f2tff(v3);
        qah[kk][0] = __float_as_uint(h0); qal[kk][0] = f2tf(v0 - h0);
        qah[kk][1] = __float_as_uint(h1); qal[kk][1] = f2tf(v1 - h1);
        qah[kk][2] = __float_as_uint(h2); qal[kk][2] = f2tf(v2 - h2);
        qah[kk][3] = __float_as_uint(h3); qal[kk][3] = f2tf(v3 - h3);
    }

    float o[8][4];
#pragma unroll
    for (int dt = 0; dt < 8; dt++)
#pragma unroll
        for (int i = 0; i < 4; i++) o[dt][i] = 0.f;
    float m0 = -1e30f, m1 = -1e30f, l0 = 0.f, l1 = 0.f;

    for (int kt = 0; kt < 16; kt++) {
        __syncthreads();
        // Tile load: K hi/lo (split ONCE here), V hi
#pragma unroll
        for (int i = 0; i < 8; i++) {
            const int idx = i * 128 + tid;          // 0..1023
            const int row = idx >> 4;
            const int c4 = (idx & 15) * 4;
            float4 kv = *(const float4*)(kg + (size_t)(kt * 64 + row) * HDIM + c4);
            float4 hh = hi4(kv);
            *(float4*)(ksh + row * KPITCH + c4) = hh;
            *(float4*)(ksl + row * KPITCH + c4) = lo4(kv, hh);
            float4 vv = *(const float4*)(vg + (size_t)(kt * 64 + row) * HDIM + c4);
            *(float4*)(vsh + row * VPITCH + c4) = hi4(vv);
        }
        __syncthreads();

        // S = Q K^T (tf32x3)
        float s[8][4];
#pragma unroll
        for (int nt = 0; nt < 8; nt++)
#pragma unroll
            for (int i = 0; i < 4; i++) s[nt][i] = 0.f;
#pragma unroll
        for (int kk = 0; kk < 8; kk++) {
#pragma unroll
            for (int nt = 0; nt < 8; nt++) {
                const int base = (nt * 8 + gid) * KPITCH + kk * 8;
                unsigned bh[2], bl[2];
                bh[0] = __float_as_uint(ksh[base + tig]);
                bh[1] = __float_as_uint(ksh[base + tig + 4]);
                bl[0] = __float_as_uint(ksl[base + tig]);
                bl[1] = __float_as_uint(ksl[base + tig + 4]);
                mma8(s[nt], qah[kk], bh);
                mma8(s[nt], qah[kk], bl);
                mma8(s[nt], qal[kk], bh);
            }
        }

        // Online softmax
        float mx0 = -1e30f, mx1 = -1e30f;
#pragma unroll
        for (int nt = 0; nt < 8; nt++) {
            mx0 = fmaxf(mx0, fmaxf(s[nt][0], s[nt][1]));
            mx1 = fmaxf(mx1, fmaxf(s[nt][2], s[nt][3]));
        }
        mx0 = fmaxf(mx0, __shfl_xor_sync(0xffffffffu, mx0, 1));
        mx0 = fmaxf(mx0, __shfl_xor_sync(0xffffffffu, mx0, 2));
        mx1 = fmaxf(mx1, __shfl_xor_sync(0xffffffffu, mx1, 1));
        mx1 = fmaxf(mx1, __shfl_xor_sync(0xffffffffu, mx1, 2));
        const float nm0 = fmaxf(m0, mx0), nm1 = fmaxf(m1, mx1);
        const float sc0 = __expf(m0 - nm0), sc1 = __expf(m1 - nm1);
        float rs0 = 0.f, rs1 = 0.f;
#pragma unroll
        for (int nt = 0; nt < 8; nt++) {
            s[nt][0] = __expf(s[nt][0] - nm0); rs0 += s[nt][0];
            s[nt][1] = __expf(s[nt][1] - nm0); rs0 += s[nt][1];
            s[nt][2] = __expf(s[nt][2] - nm1); rs1 += s[nt][2];
            s[nt][3] = __expf(s[nt][3] - nm1); rs1 += s[nt][3];
        }
        rs0 += __shfl_xor_sync(0xffffffffu, rs0, 1);
        rs0 += __shfl_xor_sync(0xffffffffu, rs0, 2);
        rs1 += __shfl_xor_sync(0xffffffffu, rs1, 1);
        rs1 += __shfl_xor_sync(0xffffffffu, rs1, 2);
        l0 = l0 * sc0 + rs0;
        l1 = l1 * sc1 + rs1;
#pragma unroll
        for (int dt = 0; dt < 8; dt++) {
            o[dt][0] *= sc0; o[dt][1] *= sc0;
            o[dt][2] *= sc1; o[dt][3] *= sc1;
        }
        m0 = nm0; m1 = nm1;

        // P -> per-warp smem (single tf32), re-fragment as A for P*V
#pragma unroll
        for (int nt = 0; nt < 8; nt++) {
            const int c0 = nt * 8 + 2 * tig;
            pw[gid * PPITCH + c0]           = f2tff(s[nt][0]);
            pw[gid * PPITCH + c0 + 1]       = f2tff(s[nt][1]);
            pw[(gid + 8) * PPITCH + c0]     = f2tff(s[nt][2]);
            pw[(gid + 8) * PPITCH + c0 + 1] = f2tff(s[nt][3]);
        }
        __syncwarp();

#pragma unroll
        for (int ks2 = 0; ks2 < 8; ks2++) {
            unsigned pa[4];
            pa[0] = __float_as_uint(pw[gid * PPITCH + ks2 * 8 + tig]);
            pa[1] = __float_as_uint(pw[(gid + 8) * PPITCH + ks2 * 8 + tig]);
            pa[2] = __float_as_uint(pw[gid * PPITCH + ks2 * 8 + tig + 4]);
            pa[3] = __float_as_uint(pw[(gid + 8) * PPITCH + ks2 * 8 + tig + 4]);
#pragma unroll
            for (int dt = 0; dt < 8; dt++) {
                unsigned bb[2];
                bb[0] = __float_as_uint(vsh[(ks2 * 8 + tig) * VPITCH + dt * 8 + gid]);
                bb[1] = __float_as_uint(vsh[(ks2 * 8 + tig + 4) * VPITCH + dt * 8 + gid]);
                mma8(o[dt], pa, bb);
            }
        }
    }

    const float inv0 = 1.f / l0, inv1 = 1.f / l1;
    const size_t base0 = ((size_t)(batch * NSEQ + r0)) * EMB + h * HDIM;
#pragma unroll
    for (int dt = 0; dt < 8; dt++) {
        const int d = dt * 8 + 2 * tig;
        *(float2*)(out + base0 + d) = make_float2(o[dt][0] * inv0, o[dt][1] * inv0);
        *(float2*)(out + base0 + (size_t)8 * EMB + d) =
            make_float2(o[dt][2] * inv1, o[dt][3] * inv1);
    }
}

// ---------------------------------------------------------------------------
// In-place output projection (tf32x2: ctx split hi/lo, Wo single tf32).
// ---------------------------------------------------------------------------
__global__ __launch_bounds__(256) void outproj_kernel(
    float* __restrict__ io, const float* __restrict__ wo, const float* __restrict__ bo)
{
    __shared__ float Ash[32 * 36];
    __shared__ float Asl[32 * 36];

    const int tid = threadIdx.x;
    const int lane = tid & 31;
    const int w = tid >> 5;
    const int gid = lane >> 2;
    const int tig = lane & 3;
    const int strip = blockIdx.x * 32;

    const int arow = tid >> 3;
    const int acol = (tid & 7) * 4;
    const float* Ag = io + (size_t)(strip + arow) * EMB + acol;

    float acc[2][12][4];
#pragma unroll
    for (int mt = 0; mt < 2; mt++)
#pragma unroll
        for (int nt = 0; nt < 12; nt++)
#pragma unroll
            for (int i = 0; i < 4; i++) acc[mt][nt][i] = 0.f;

    float4 va = *(const float4*)(Ag);

    for (int kt = 0; kt < 24; kt++) {
        __syncthreads();
        {
            float4 hh = hi4(va);
            *(float4*)(Ash + arow * 36 + acol) = hh;
            *(float4*)(Asl + arow * 36 + acol) = lo4(va, hh);
        }
        __syncthreads();
        if (kt + 1 < 24) va = *(const float4*)(Ag + (kt + 1) * 32);

#pragma unroll
        for (int ks = 0; ks < 4; ks++) {
            unsigned afh[2][4], afl[2][4];
#pragma unroll
            for (int mt = 0; mt < 2; mt++) {
                const int base = (mt * 16) * 36 + ks * 8;
                afh[mt][0] = __float_as_uint(Ash[base + gid * 36 + tig]);
                afh[mt][1] = __float_as_uint(Ash[base + (gid + 8) * 36 + tig]);
                afh[mt][2] = __float_as_uint(Ash[base + gid * 36 + tig + 4]);
                afh[mt][3] = __float_as_uint(Ash[base + (gid + 8) * 36 + tig + 4]);
                afl[mt][0] = __float_as_uint(Asl[base + gid * 36 + tig]);
                afl[mt][1] = __float_as_uint(Asl[base + (gid + 8) * 36 + tig]);
                afl[mt][2] = __float_as_uint(Asl[base + gid * 36 + tig + 4]);
                afl[mt][3] = __float_as_uint(Asl[base + (gid + 8) * 36 + tig + 4]);
            }
#pragma unroll
            for (int nt = 0; nt < 12; nt++) {
                const int col = w * 96 + nt * 8 + gid;
                const float* bp = wo + (size_t)col * EMB + kt * 32 + ks * 8;
                unsigned bh[2];
                bh[0] = f2tf(bp[tig]);
                bh[1] = f2tf(bp[tig + 4]);
#pragma unroll
                for (int mt = 0; mt < 2; mt++) {
                    mma8(acc[mt][nt], afh[mt], bh);
                    mma8(acc[mt][nt], afl[mt], bh);
                }
            }
        }
    }

    __syncthreads();   // all in-place reads complete before any write

#pragma unroll
    for (int mt = 0; mt < 2; mt++) {
#pragma unroll
        for (int nt = 0; nt < 12; nt++) {
            const int row = strip + mt * 16 + gid;
            const int col = w * 96 + nt * 8 + 2 * tig;
            const float b0 = bo[col], b1 = bo[col + 1];
            *(float2*)(io + (size_t)row * EMB + col) =
                make_float2(acc[mt][nt][0] + b0, acc[mt][nt][1] + b1);
            *(float2*)(io + (size_t)(row + 8) * EMB + col) =
                make_float2(acc[mt][nt][2] + b0, acc[mt][nt][3] + b1);
        }
    }
}

// ---------------------------------------------------------------------------
// Launch: ping-pong pipeline. QKV(b) -> slot b&1 on stream0; flash(b) reads
// slot b&1 on s1. QKV(b) additionally waits flash(b-2) (same slot drained).
// outproj joins after the last flash. Graph-capturable fork/join via events.
// ---------------------------------------------------------------------------
extern "C" void kernel_launch(void* const* d_in, const int* in_sizes, int n_in,
                              void* d_out, int out_size)
{
    const float* x  = (const float*)d_in[0];
    const float* wq = (const float*)d_in[1];
    const float* bq = (const float*)d_in[2];
    const float* wk = (const float*)d_in[3];
    const float* bk = (const float*)d_in[4];
    const float* wv = (const float*)d_in[5];
    const float* bv = (const float*)d_in[6];
    const float* wo = (const float*)d_in[7];
    const float* bo = (const float*)d_in[8];
    float* out = (float*)d_out;

    static cudaStream_t s1 = nullptr;
    static cudaEvent_t evQ[BATCH], evF[BATCH];
    if (s1 == nullptr) {
        cudaStreamCreateWithFlags(&s1, cudaStreamNonBlocking);
        for (int i = 0; i < BATCH; i++) {
            cudaEventCreateWithFlags(&evQ[i], cudaEventDisableTiming);
            cudaEventCreateWithFlags(&evF[i], cudaEventDisableTiming);
        }
        cudaFuncSetAttribute(qkv_gemm_kernel,
                             cudaFuncAttributeMaxDynamicSharedMemorySize, GEMM_SMEM);
        cudaFuncSetAttribute(flash_kernel,
                             cudaFuncAttributeMaxDynamicSharedMemorySize, FLASH_SMEM);
        cudaFuncSetAttribute(flash_kernel,
                             cudaFuncAttributePreferredSharedMemoryCarveout, 100);
    }

    for (int b = 0; b < BATCH; b++) {
        const int buf = b & 1;
        // Anti-dependency: slot `buf` must be drained by flash(b-2) first.
        if (b >= 2) cudaStreamWaitEvent(0, evF[b - 2], 0);
        dim3 ggrid(18, 8);
        qkv_gemm_kernel<<<ggrid, 256, GEMM_SMEM>>>(x, wq, bq, wk, bk, wv, bv, b, buf);
        cudaEventRecord(evQ[b], 0);
        // flash(b) waits for QKV(b); runs on s1, overlapping QKV(b+1).
        cudaStreamWaitEvent(s1, evQ[b], 0);
        dim3 fgrid(16, NHEADS);
        flash_kernel<<<fgrid, 128, FLASH_SMEM, s1>>>(out, b, buf);
        cudaEventRecord(evF[b], s1);
    }
    // Join: s1 is in-order, so the last flash event covers all of them.
    cudaStreamWaitEvent(0, evF[BATCH - 1], 0);
    outproj_kernel<<<MTOT / 32, 256>>>(out, wo, bo);
}

// round 14
// speedup vs baseline: 1.2508x; 1.2508x over previous
#include <cuda_runtime.h>
#include <cstdint>
#include <cstdlib>

#define BATCH   8
#define NSEQ    1024
#define EMB     768
#define NHEADS  12
#define HDIM    64
#define MTOT    (BATCH * NSEQ)
#define HSTRIDE (NSEQ * HDIM)                 // 65536
#define SLOT2   (2 * 3 * NHEADS * NSEQ * HDIM) // one 2-batch slot (9.4 MiB floats)

// Scratch: TWO ping-pong slots of TWO batches each = 37.7 MiB.
// Per slot layout: [lb(2)][sel(3)][head(12)][n(1024)][d(64)]
__device__ float g_s[2 * SLOT2];

namespace {
struct EagerLoad { EagerLoad() { setenv("CUDA_MODULE_LOADING", "EAGER", 1); } };
EagerLoad eager_load_instance_;
}

// ---------------------------------------------------------------------------
// tf32 helpers
// ---------------------------------------------------------------------------
__device__ __forceinline__ unsigned f2tf(float x) {
    unsigned r;
    asm("cvt.rna.tf32.f32 %0, %1;" : "=r"(r) : "f"(x));
    return r;
}
__device__ __forceinline__ float f2tff(float x) { return __uint_as_float(f2tf(x)); }

__device__ __forceinline__ void mma8(float* c, const unsigned* a, const unsigned* b) {
    asm volatile(
        "mma.sync.aligned.m16n8k8.row.col.f32.tf32.tf32.f32 "
        "{%0,%1,%2,%3}, {%4,%5,%6,%7}, {%8,%9}, {%0,%1,%2,%3};\n"
        : "+f"(c[0]), "+f"(c[1]), "+f"(c[2]), "+f"(c[3])
        : "r"(a[0]), "r"(a[1]), "r"(a[2]), "r"(a[3]), "r"(b[0]), "r"(b[1]));
}

__device__ __forceinline__ float4 hi4(float4 v) {
    return make_float4(f2tff(v.x), f2tff(v.y), f2tff(v.z), f2tff(v.w));
}
__device__ __forceinline__ float4 lo4(float4 v, float4 h) {
    return make_float4(f2tff(v.x - h.x), f2tff(v.y - h.y),
                       f2tff(v.z - h.z), f2tff(v.w - h.w));
}

// ---------------------------------------------------------------------------
// Fused QKV GEMM (tf32x2: x hi+lo at fragment load, W hi only) for TWO
// batches. Grid (18, 16). Writes into ping-pong slot `buf`.
// ---------------------------------------------------------------------------
#define GEMM_SMEM (4 * 128 * 36 * 4)   // Araw[2] + Bh[2] = 73728 B

__global__ __launch_bounds__(256) void qkv_gemm_kernel(
    const float* __restrict__ x,
    const float* __restrict__ wq, const float* __restrict__ bq,
    const float* __restrict__ wk, const float* __restrict__ bk,
    const float* __restrict__ wv, const float* __restrict__ bv,
    int group, int buf)
{
    extern __shared__ float sm[];
    float* Ar = sm;                    // [2][128*36] raw fp32
    float* Bh = sm + 2 * 128 * 36;     // [2][128*36] tf32-hi

    const int bx = blockIdx.x;         // 0..17
    const int by = blockIdx.y;         // 0..15
    const int sel = bx / 6;
    const int bxx = bx % 6;
    const float* W    = (sel == 0) ? wq : (sel == 1) ? wk : wv;
    const float* bias = (sel == 0) ? bq : (sel == 1) ? bk : bv;
    const float* A = x + (size_t)(group * 2 * NSEQ) * EMB;

    const int tid = threadIdx.x;
    const int lane = tid & 31;
    const int w = tid >> 5;
    const int wm = w & 3;
    const int wn = w >> 2;
    const int gid = lane >> 2;
    const int tig = lane & 3;

    const int lrow = tid >> 1;
    const int lcol = (tid & 1) * 16;

    const float* Ag = A + (size_t)(by * 128 + lrow) * EMB + lcol;
    const float* Wg = W + (size_t)(bxx * 128 + lrow) * EMB + lcol;

    float acc[2][8][4];
#pragma unroll
    for (int mt = 0; mt < 2; mt++)
#pragma unroll
        for (int nt = 0; nt < 8; nt++)
#pragma unroll
            for (int i = 0; i < 4; i++) acc[mt][nt][i] = 0.f;

    float4 ra[4], rb[4];
#pragma unroll
    for (int j = 0; j < 4; j++) {
        ra[j] = *(const float4*)(Ag + j * 4);
        rb[j] = *(const float4*)(Wg + j * 4);
    }
#pragma unroll
    for (int j = 0; j < 4; j++) {
        *(float4*)(Ar + lrow * 36 + lcol + j * 4) = ra[j];
        *(float4*)(Bh + lrow * 36 + lcol + j * 4) = hi4(rb[j]);
    }
    __syncthreads();

    const int NKT = EMB / 32;   // 24
    for (int kt = 0; kt < NKT; kt++) {
        const int cur = kt & 1;
        if (kt + 1 < NKT) {
#pragma unroll
            for (int j = 0; j < 4; j++) {
                ra[j] = *(const float4*)(Ag + (kt + 1) * 32 + j * 4);
                rb[j] = *(const float4*)(Wg + (kt + 1) * 32 + j * 4);
            }
        }
        const float* Ab = Ar + cur * 128 * 36;
        const float* Bb = Bh + cur * 128 * 36;
#pragma unroll
        for (int ks = 0; ks < 4; ks++) {
            unsigned afh[2][4], afl[2][4], bfh[8][2];
#pragma unroll
            for (int mt = 0; mt < 2; mt++) {
                const int base = (wm * 32 + mt * 16) * 36 + ks * 8;
                float a0 = Ab[base + gid * 36 + tig];
                float a1 = Ab[base + (gid + 8) * 36 + tig];
                float a2 = Ab[base + gid * 36 + tig + 4];
                float a3 = Ab[base + (gid + 8) * 36 + tig + 4];
                float h0 = f2tff(a0), h1 = f2tff(a1), h2 = f2tff(a2), h3 = f2tff(a3);
                afh[mt][0] = __float_as_uint(h0); afl[mt][0] = f2tf(a0 - h0);
                afh[mt][1] = __float_as_uint(h1); afl[mt][1] = f2tf(a1 - h1);
                afh[mt][2] = __float_as_uint(h2); afl[mt][2] = f2tf(a2 - h2);
                afh[mt][3] = __float_as_uint(h3); afl[mt][3] = f2tf(a3 - h3);
            }
#pragma unroll
            for (int nt = 0; nt < 8; nt++) {
                const int base = (wn * 64 + nt * 8 + gid) * 36 + ks * 8;
                bfh[nt][0] = __float_as_uint(Bb[base + tig]);
                bfh[nt][1] = __float_as_uint(Bb[base + tig + 4]);
            }
#pragma unroll
            for (int mt = 0; mt < 2; mt++)
#pragma unroll
                for (int nt = 0; nt < 8; nt++) {
                    mma8(acc[mt][nt], afh[mt], bfh[nt]);
                    mma8(acc[mt][nt], afl[mt], bfh[nt]);
                }
        }
        if (kt + 1 < NKT) {
            const int nxt = cur ^ 1;
#pragma unroll
            for (int j = 0; j < 4; j++) {
                *(float4*)(Ar + nxt * 128 * 36 + lrow * 36 + lcol + j * 4) = ra[j];
                *(float4*)(Bh + nxt * 128 * 36 + lrow * 36 + lcol + j * 4) = hi4(rb[j]);
            }
            __syncthreads();
        }
    }

#pragma unroll
    for (int mt = 0; mt < 2; mt++) {
        const int grow = by * 128 + wm * 32 + mt * 16 + gid;   // 0..2047
        const int lb = grow >> 10;
        const int n = grow & 1023;
#pragma unroll
        for (int nt = 0; nt < 8; nt++) {
            const int wcol = bxx * 128 + wn * 64 + nt * 8 + 2 * tig;
            const float b0 = bias[wcol], b1 = bias[wcol + 1];
            const int h_ = wcol >> 6, d_ = wcol & 63;
            float* dst = g_s + (size_t)buf * SLOT2 +
                (((size_t)(lb * 3 + sel) * NHEADS + h_) * NSEQ + n) * HDIM + d_;
            *(float2*)dst = make_float2(acc[mt][nt][0] + b0, acc[mt][nt][1] + b1);
            *(float2*)(dst + 8 * HDIM) =
                make_float2(acc[mt][nt][2] + b0, acc[mt][nt][3] + b1);
        }
    }
}

// ---------------------------------------------------------------------------
// Flash attention for TWO batches from slot `buf`: S = QK^T tf32x3 (K hi/lo
// precomputed at tile load), P*V single tf32. Grid (16, 12, 2); 128 threads.
// ---------------------------------------------------------------------------
#define KPITCH 68
#define VPITCH 72
#define PPITCH 68
#define FLASH_SMEM ((2 * 64 * KPITCH + 64 * VPITCH + 4 * 16 * PPITCH) * 4)  // 70656

__global__ __launch_bounds__(128, 3) void flash_kernel(
    float* __restrict__ out, int group, int buf)
{
    extern __shared__ float sm[];
    float* ksh = sm;                         // [64][68] K hi
    float* ksl = ksh + 64 * KPITCH;          // [64][68] K lo
    float* vsh = ksl + 64 * KPITCH;          // [64][72] V hi
    float* psh = vsh + 64 * VPITCH;          // [4][16][68] P

    const int h = blockIdx.y;
    const int lb = blockIdx.z;
    const int q0 = blockIdx.x * 64;
    const int tid = threadIdx.x;
    const int lane = tid & 31;
    const int w = tid >> 5;                  // 0..3
    const int gid = lane >> 2;
    const int tig = lane & 3;
    float* pw = psh + w * 16 * PPITCH;

    const float* base_s = g_s + (size_t)buf * SLOT2;
    const float* qg = base_s + ((size_t)(lb * 3 + 0) * NHEADS + h) * HSTRIDE;
    const float* kg = base_s + ((size_t)(lb * 3 + 1) * NHEADS + h) * HSTRIDE;
    const float* vg = base_s + ((size_t)(lb * 3 + 2) * NHEADS + h) * HSTRIDE;

    const int r0 = q0 + w * 16 + gid;

    // Q fragments hi/lo in registers (reused across all 16 key tiles)
    unsigned qah[8][4], qal[8][4];
#pragma unroll
    for (int kk = 0; kk < 8; kk++) {
        const int c = kk * 8 + tig;
        float v0 = qg[(size_t)r0 * HDIM + c];
        float v1 = qg[(size_t)(r0 + 8) * HDIM + c];
        float v2 = qg[(size_t)r0 * HDIM + c + 4];
        float v3 = qg[(size_t)(r0 + 8) * HDIM + c + 4];
        float h0 = f2tff(v0), h1 = f2tff(v1), h2 = f2tff(v2), h3 = f2tff(v3);
        qah[kk][0] = __float_as_uint(h0); qal[kk][0] = f2tf(v0 - h0);
        qah[kk][1] = __float_as_uint(h1); qal[kk][1] = f2tf(v1 - h1);
        qah[kk][2] = __float_as_uint(h2); qal[kk][2] = f2tf(v2 - h2);
        qah[kk][3] = __float_as_uint(h3); qal[kk][3] = f2tf(v3 - h3);
    }

    float o[8][4];
#pragma unroll
    for (int dt = 0; dt < 8; dt++)
#pragma unroll
        for (int i = 0; i < 4; i++) o[dt][i] = 0.f;
    float m0 = -1e30f, m1 = -1e30f, l0 = 0.f, l1 = 0.f;

    for (int kt = 0; kt < 16; kt++) {
        __syncthreads();
        // Tile load: K hi/lo (split ONCE here), V hi
#pragma unroll
        for (int i = 0; i < 8; i++) {
            const int idx = i * 128 + tid;          // 0..1023
            const int row = idx >> 4;
            const int c4 = (idx & 15) * 4;
            float4 kv = *(const float4*)(kg + (size_t)(kt * 64 + row) * HDIM + c4);
            float4 hh = hi4(kv);
            *(float4*)(ksh + row * KPITCH + c4) = hh;
            *(float4*)(ksl + row * KPITCH + c4) = lo4(kv, hh);
            float4 vv = *(const float4*)(vg + (size_t)(kt * 64 + row) * HDIM + c4);
            *(float4*)(vsh + row * VPITCH + c4) = hi4(vv);
        }
        __syncthreads();

        // S = Q K^T (tf32x3)
        float s[8][4];
#pragma unroll
        for (int nt = 0; nt < 8; nt++)
#pragma unroll
            for (int i = 0; i < 4; i++) s[nt][i] = 0.f;
#pragma unroll
        for (int kk = 0; kk < 8; kk++) {
#pragma unroll
            for (int nt = 0; nt < 8; nt++) {
                const int base = (nt * 8 + gid) * KPITCH + kk * 8;
                unsigned bh[2], bl[2];
                bh[0] = __float_as_uint(ksh[base + tig]);
                bh[1] = __float_as_uint(ksh[base + tig + 4]);
                bl[0] = __float_as_uint(ksl[base + tig]);
                bl[1] = __float_as_uint(ksl[base + tig + 4]);
                mma8(s[nt], qah[kk], bh);
                mma8(s[nt], qah[kk], bl);
                mma8(s[nt], qal[kk], bh);
            }
        }

        // Online softmax
        float mx0 = -1e30f, mx1 = -1e30f;
#pragma unroll
        for (int nt = 0; nt < 8; nt++) {
            mx0 = fmaxf(mx0, fmaxf(s[nt][0], s[nt][1]));
            mx1 = fmaxf(mx1, fmaxf(s[nt][2], s[nt][3]));
        }
        mx0 = fmaxf(mx0, __shfl_xor_sync(0xffffffffu, mx0, 1));
        mx0 = fmaxf(mx0, __shfl_xor_sync(0xffffffffu, mx0, 2));
        mx1 = fmaxf(mx1, __shfl_xor_sync(0xffffffffu, mx1, 1));
        mx1 = fmaxf(mx1, __shfl_xor_sync(0xffffffffu, mx1, 2));
        const float nm0 = fmaxf(m0, mx0), nm1 = fmaxf(m1, mx1);
        const float sc0 = __expf(m0 - nm0), sc1 = __expf(m1 - nm1);
        float rs0 = 0.f, rs1 = 0.f;
#pragma unroll
        for (int nt = 0; nt < 8; nt++) {
            s[nt][0] = __expf(s[nt][0] - nm0); rs0 += s[nt][0];
            s[nt][1] = __expf(s[nt][1] - nm0); rs0 += s[nt][1];
            s[nt][2] = __expf(s[nt][2] - nm1); rs1 += s[nt][2];
            s[nt][3] = __expf(s[nt][3] - nm1); rs1 += s[nt][3];
        }
        rs0 += __shfl_xor_sync(0xffffffffu, rs0, 1);
        rs0 += __shfl_xor_sync(0xffffffffu, rs0, 2);
        rs1 += __shfl_xor_sync(0xffffffffu, rs1, 1);
        rs1 += __shfl_xor_sync(0xffffffffu, rs1, 2);
        l0 = l0 * sc0 + rs0;
        l1 = l1 * sc1 + rs1;
#pragma unroll
        for (int dt = 0; dt < 8; dt++) {
            o[dt][0] *= sc0; o[dt][1] *= sc0;
            o[dt][2] *= sc1; o[dt][3] *= sc1;
        }
        m0 = nm0; m1 = nm1;

        // P -> per-warp smem (single tf32), re-fragment as A for P*V
#pragma unroll
        for (int nt = 0; nt < 8; nt++) {
            const int c0 = nt * 8 + 2 * tig;
            pw[gid * PPITCH + c0]           = f2tff(s[nt][0]);
            pw[gid * PPITCH + c0 + 1]       = f2tff(s[nt][1]);
            pw[(gid + 8) * PPITCH + c0]     = f2tff(s[nt][2]);
            pw[(gid + 8) * PPITCH + c0 + 1] = f2tff(s[nt][3]);
        }
        __syncwarp();

#pragma unroll
        for (int ks2 = 0; ks2 < 8; ks2++) {
            unsigned pa[4];
            pa[0] = __float_as_uint(pw[gid * PPITCH + ks2 * 8 + tig]);
            pa[1] = __float_as_uint(pw[(gid + 8) * PPITCH + ks2 * 8 + tig]);
            pa[2] = __float_as_uint(pw[gid * PPITCH + ks2 * 8 + tig + 4]);
            pa[3] = __float_as_uint(pw[(gid + 8) * PPITCH + ks2 * 8 + tig + 4]);
#pragma unroll
            for (int dt = 0; dt < 8; dt++) {
                unsigned bb[2];
                bb[0] = __float_as_uint(vsh[(ks2 * 8 + tig) * VPITCH + dt * 8 + gid]);
                bb[1] = __float_as_uint(vsh[(ks2 * 8 + tig + 4) * VPITCH + dt * 8 + gid]);
                mma8(o[dt], pa, bb);
            }
        }
    }

    const float inv0 = 1.f / l0, inv1 = 1.f / l1;
    const size_t base0 =
        ((size_t)((group * 2 + lb) * NSEQ + r0)) * EMB + h * HDIM;
#pragma unroll
    for (int dt = 0; dt < 8; dt++) {
        const int d = dt * 8 + 2 * tig;
        *(float2*)(out + base0 + d) = make_float2(o[dt][0] * inv0, o[dt][1] * inv0);
        *(float2*)(out + base0 + (size_t)8 * EMB + d) =
            make_float2(o[dt][2] * inv1, o[dt][3] * inv1);
    }
}

// ---------------------------------------------------------------------------
// In-place output projection (tf32x2). Chunked: grid 64 CTAs covers the
// 2048 rows of one batch-group; `chunk` selects which group's rows.
// CTA = 32-row strip x full 768 cols; all reads precede all writes.
// ---------------------------------------------------------------------------
__global__ __launch_bounds__(256) void outproj_kernel(
    float* __restrict__ io, const float* __restrict__ wo,
    const float* __restrict__ bo, int chunk)
{
    __shared__ float Ash[32 * 36];
    __shared__ float Asl[32 * 36];

    const int tid = threadIdx.x;
    const int lane = tid & 31;
    const int w = tid >> 5;
    const int gid = lane >> 2;
    const int tig = lane & 3;
    const int strip = (chunk * 64 + blockIdx.x) * 32;

    const int arow = tid >> 3;
    const int acol = (tid & 7) * 4;
    const float* Ag = io + (size_t)(strip + arow) * EMB + acol;

    float acc[2][12][4];
#pragma unroll
    for (int mt = 0; mt < 2; mt++)
#pragma unroll
        for (int nt = 0; nt < 12; nt++)
#pragma unroll
            for (int i = 0; i < 4; i++) acc[mt][nt][i] = 0.f;

    float4 va = *(const float4*)(Ag);

    for (int kt = 0; kt < 24; kt++) {
        __syncthreads();
        {
            float4 hh = hi4(va);
            *(float4*)(Ash + arow * 36 + acol) = hh;
            *(float4*)(Asl + arow * 36 + acol) = lo4(va, hh);
        }
        __syncthreads();
        if (kt + 1 < 24) va = *(const float4*)(Ag + (kt + 1) * 32);

#pragma unroll
        for (int ks = 0; ks < 4; ks++) {
            unsigned afh[2][4], afl[2][4];
#pragma unroll
            for (int mt = 0; mt < 2; mt++) {
                const int base = (mt * 16) * 36 + ks * 8;
                afh[mt][0] = __float_as_uint(Ash[base + gid * 36 + tig]);
                afh[mt][1] = __float_as_uint(Ash[base + (gid + 8) * 36 + tig]);
                afh[mt][2] = __float_as_uint(Ash[base + gid * 36 + tig + 4]);
                afh[mt][3] = __float_as_uint(Ash[base + (gid + 8) * 36 + tig + 4]);
                afl[mt][0] = __float_as_uint(Asl[base + gid * 36 + tig]);
                afl[mt][1] = __float_as_uint(Asl[base + (gid + 8) * 36 + tig]);
                afl[mt][2] = __float_as_uint(Asl[base + gid * 36 + tig + 4]);
                afl[mt][3] = __float_as_uint(Asl[base + (gid + 8) * 36 + tig + 4]);
            }
#pragma unroll
            for (int nt = 0; nt < 12; nt++) {
                const int col = w * 96 + nt * 8 + gid;
                const float* bp = wo + (size_t)col * EMB + kt * 32 + ks * 8;
                unsigned bh[2];
                bh[0] = f2tf(bp[tig]);
                bh[1] = f2tf(bp[tig + 4]);
#pragma unroll
                for (int mt = 0; mt < 2; mt++) {
                    mma8(acc[mt][nt], afh[mt], bh);
                    mma8(acc[mt][nt], afl[mt], bh);
                }
            }
        }
    }

    __syncthreads();   // all in-place reads complete before any write

#pragma unroll
    for (int mt = 0; mt < 2; mt++) {
#pragma unroll
        for (int nt = 0; nt < 12; nt++) {
            const int row = strip + mt * 16 + gid;
            const int col = w * 96 + nt * 8 + 2 * tig;
            const float b0 = bo[col], b1 = bo[col + 1];
            *(float2*)(io + (size_t)row * EMB + col) =
                make_float2(acc[mt][nt][0] + b0, acc[mt][nt][1] + b1);
            *(float2*)(io + (size_t)(row + 8) * EMB + col) =
                make_float2(acc[mt][nt][2] + b0, acc[mt][nt][3] + b1);
        }
    }
}

// ---------------------------------------------------------------------------
// Launch: ping-pong pipelined graph.
//   stream0: QKV(g) -> slot g&1   (waits flash(g-2): slot drained)
//   s1:      flash(g) reads slot g&1 (waits QKV(g)); overlaps QKV(g+1)
//   s2:      outproj chunk g (waits flash(g)); overlaps everything later
// Final join: stream0 waits all outproj chunks.
// ---------------------------------------------------------------------------
extern "C" void kernel_launch(void* const* d_in, const int* in_sizes, int n_in,
                              void* d_out, int out_size)
{
    const float* x  = (const float*)d_in[0];
    const float* wq = (const float*)d_in[1];
    const float* bq = (const float*)d_in[2];
    const float* wk = (const float*)d_in[3];
    const float* bk = (const float*)d_in[4];
    const float* wv = (const float*)d_in[5];
    const float* bv = (const float*)d_in[6];
    const float* wo = (const float*)d_in[7];
    const float* bo = (const float*)d_in[8];
    float* out = (float*)d_out;

    static cudaStream_t s1 = nullptr, s2 = nullptr;
    static cudaEvent_t evQ[4], evF[4], evO[4];
    if (s1 == nullptr) {
        cudaStreamCreateWithFlags(&s1, cudaStreamNonBlocking);
        cudaStreamCreateWithFlags(&s2, cudaStreamNonBlocking);
        for (int i = 0; i < 4; i++) {
            cudaEventCreateWithFlags(&evQ[i], cudaEventDisableTiming);
            cudaEventCreateWithFlags(&evF[i], cudaEventDisableTiming);
            cudaEventCreateWithFlags(&evO[i], cudaEventDisableTiming);
        }
        cudaFuncSetAttribute(qkv_gemm_kernel,
                             cudaFuncAttributeMaxDynamicSharedMemorySize, GEMM_SMEM);
        cudaFuncSetAttribute(flash_kernel,
                             cudaFuncAttributeMaxDynamicSharedMemorySize, FLASH_SMEM);
        // NOTE: no PreferredSharedMemoryCarveout — it blocks co-residency.
    }

    for (int g = 0; g < 4; g++) {
        const int buf = g & 1;
        if (g >= 2) cudaStreamWaitEvent(0, evF[g - 2], 0);   // slot drained
        dim3 ggrid(18, 16);
        qkv_gemm_kernel<<<ggrid, 256, GEMM_SMEM>>>(x, wq, bq, wk, bk, wv, bv, g, buf);
        cudaEventRecord(evQ[g], 0);

        cudaStreamWaitEvent(s1, evQ[g], 0);
        dim3 fgrid(16, NHEADS, 2);
        flash_kernel<<<fgrid, 128, FLASH_SMEM, s1>>>(out, g, buf);
        cudaEventRecord(evF[g], s1);

        cudaStreamWaitEvent(s2, evF[g], 0);
        outproj_kernel<<<64, 256, 0, s2>>>(out, wo, bo, g);
        cudaEventRecord(evO[g], s2);
    }
    for (int g = 0; g < 4; g++)
        cudaStreamWaitEvent(0, evO[g], 0);
}